// round 12
// baseline (speedup 1.0000x reference)
#include <cuda_runtime.h>
#include <cuda_bf16.h>
#include <cuda_fp16.h>
#include <math.h>
#include <float.h>
#include <cstdint>

#define BB 8192
#define DD 1024
#define NN 4096
#define LRC 0.02f
#define ATC 0.3f
#define ACOEF 0.002f
#define EPSDS 0.5f
#define MARGIN 2e-3f

// ---------------- device scratch ----------------
__device__ unsigned long long g_best[BB];
__device__ float g_x2[BB];
__device__ float g_w2[NN];
__device__ float g_rsum[NN];
__device__ float g_counts[NN];
__device__ unsigned int g_tilemax[BB * 32];   // per (row, 128-wide N tile) act max (f32 bits)
__device__ __nv_bfloat16 g_xb[BB * DD];       // 16 MB
__device__ __nv_bfloat16 g_wb[NN * DD];       // 8 MB
__device__ __half g_acth[(size_t)BB * NN];    // 32 MB fp16 acts

__device__ __forceinline__ uint32_t smem_u32(const void* p) {
    uint32_t a;
    asm("{ .reg .u64 t; cvta.to.shared.u64 t, %1; cvt.u32.u64 %0, t; }" : "=r"(a) : "l"(p));
    return a;
}

#define LDSM4(r0, r1, r2, r3, addr) \
    asm volatile("ldmatrix.sync.aligned.m8n8.x4.shared.b16 {%0,%1,%2,%3}, [%4];" \
                 : "=r"(r0), "=r"(r1), "=r"(r2), "=r"(r3) : "r"(addr))
#define MMA16816(c0, c1, c2, c3, a0, a1, a2, a3, b0, b1) \
    asm volatile("mma.sync.aligned.m16n8k16.row.col.f32.bf16.bf16.f32 " \
                 "{%0,%1,%2,%3}, {%4,%5,%6,%7}, {%8,%9}, {%0,%1,%2,%3};" \
                 : "+f"(c0), "+f"(c1), "+f"(c2), "+f"(c3) \
                 : "r"(a0), "r"(a1), "r"(a2), "r"(a3), "r"(b0), "r"(b1))
#define CPASYNC16(dst, src) \
    asm volatile("cp.async.ca.shared.global [%0], [%1], 16;" :: "r"(dst), "l"(src))
#define CPCOMMIT() asm volatile("cp.async.commit_group;" ::: "memory")
#define CPWAIT1() asm volatile("cp.async.wait_group 1;" ::: "memory")

static constexpr int STAGE_B = 24576;
static constexpr int GEMM_SMEM = 3 * STAGE_B;   // 73728

// ---------------------------------------------------------------------------
// K0: zero sums region + counts
// ---------------------------------------------------------------------------
__global__ void k_init(float4* __restrict__ sums4) {
    int i = blockIdx.x * blockDim.x + threadIdx.x;
    sums4[i] = make_float4(0.f, 0.f, 0.f, 0.f);
    if (i < NN) g_counts[i] = 0.f;
}

// ---------------------------------------------------------------------------
// K1: row reductions + bf16 conversion (warp per row)
// ---------------------------------------------------------------------------
__global__ void __launch_bounds__(256)
k_rowprep(const float* __restrict__ X, const float* __restrict__ W,
          const float* __restrict__ REL) {
    const int wid = threadIdx.x >> 5, l = threadIdx.x & 31;
    const int r = blockIdx.x * 8 + wid;
    float v1 = 0.f, v2 = 0.f;
    if (r < BB) {
        const float4* xr = (const float4*)(X + (size_t)r * DD);
        uint2* ob = (uint2*)(g_xb + (size_t)r * DD);
#pragma unroll
        for (int j = 0; j < 8; j++) {
            float4 v = xr[l + j * 32];
            v1 += v.x * v.x + v.y * v.y + v.z * v.z + v.w * v.w;
            __nv_bfloat162 p0 = __floats2bfloat162_rn(v.x, v.y);
            __nv_bfloat162 p1 = __floats2bfloat162_rn(v.z, v.w);
            ob[l + j * 32] = make_uint2(*(uint32_t*)&p0, *(uint32_t*)&p1);
        }
    } else {
        const int n = r - BB;
        const float4* wr = (const float4*)(W + (size_t)n * DD);
        const float4* rr = (const float4*)(REL + (size_t)n * DD);
        uint2* ob = (uint2*)(g_wb + (size_t)n * DD);
#pragma unroll
        for (int j = 0; j < 8; j++) {
            float4 v = wr[l + j * 32];
            float4 rv = rr[l + j * 32];
            v1 += v.x * v.x + v.y * v.y + v.z * v.z + v.w * v.w;
            v2 += rv.x + rv.y + rv.z + rv.w;
            __nv_bfloat162 p0 = __floats2bfloat162_rn(v.x, v.y);
            __nv_bfloat162 p1 = __floats2bfloat162_rn(v.z, v.w);
            ob[l + j * 32] = make_uint2(*(uint32_t*)&p0, *(uint32_t*)&p1);
        }
    }
#pragma unroll
    for (int o = 16; o > 0; o >>= 1) {
        v1 += __shfl_down_sync(0xFFFFFFFFu, v1, o);
        v2 += __shfl_down_sync(0xFFFFFFFFu, v2, o);
    }
    if (l == 0) {
        if (r < BB) g_x2[r] = v1;
        else { g_w2[r - BB] = v1; g_rsum[r - BB] = v2; }
    }
}

// ---------------------------------------------------------------------------
// K2: bf16 mma.sync GEMM (128x128 tile, 3-stage cp.async)
// ---------------------------------------------------------------------------
__global__ void __launch_bounds__(256, 2)
k_gemm_bf16(const float* __restrict__ NC) {
    extern __shared__ __align__(128) char sm[];
    const uint32_t sb = smem_u32(sm);

    const int tid = threadIdx.x;
    const int l = tid & 31, wid = tid >> 5;
    const int warp_m = wid >> 2, warp_n = wid & 3;
    const int mBase = blockIdx.y * 128;
    const int nBase = blockIdx.x * 128;

    const int row = tid >> 1, h = tid & 1;
    const __nv_bfloat16* xg = g_xb + (size_t)(mBase + row) * DD + h * 16;
    const __nv_bfloat16* wg = g_wb + (size_t)(nBase + row) * DD + h * 16;
    const uint32_t aDst = sb + h * 6144 + row * 48;
    const uint32_t bDst = sb + 12288 + h * 6144 + row * 48;

#pragma unroll
    for (int s = 0; s < 2; s++) {
        const __nv_bfloat16* xs = xg + s * 32;
        const __nv_bfloat16* ws = wg + s * 32;
        CPASYNC16(aDst + s * STAGE_B, xs);
        CPASYNC16(aDst + s * STAGE_B + 16, xs + 8);
        CPASYNC16(bDst + s * STAGE_B, ws);
        CPASYNC16(bDst + s * STAGE_B + 16, ws + 8);
        CPCOMMIT();
    }

    float c[4][4][4];
#pragma unroll
    for (int i = 0; i < 4; i++)
#pragma unroll
        for (int j = 0; j < 4; j++)
#pragma unroll
            for (int k = 0; k < 4; k++) c[i][j][k] = 0.f;

    const uint32_t aAddr0 = sb + (warp_m * 64 + (l & 15)) * 48 + (l >> 4) * 16;
    const int b_nt_off = (l >> 4) & 1;
    const int b_half = (l >> 3) & 1;
    const uint32_t bAddr0 = sb + 12288 +
        (warp_n * 32 + b_nt_off * 8 + (l & 7)) * 48 + b_half * 16;

    for (int kt = 0; kt < 32; kt++) {
        CPWAIT1();
        __syncthreads();
        if (kt + 2 < 32) {
            const int s = (kt + 2) % 3;
            const __nv_bfloat16* xs = xg + (kt + 2) * 32;
            const __nv_bfloat16* ws = wg + (kt + 2) * 32;
            CPASYNC16(aDst + s * STAGE_B, xs);
            CPASYNC16(aDst + s * STAGE_B + 16, xs + 8);
            CPASYNC16(bDst + s * STAGE_B, ws);
            CPASYNC16(bDst + s * STAGE_B + 16, ws + 8);
        }
        CPCOMMIT();

        const uint32_t aB = aAddr0 + (kt % 3) * STAGE_B;
        const uint32_t bB = bAddr0 + (kt % 3) * STAGE_B;
#pragma unroll
        for (int ch = 0; ch < 2; ch++) {
            uint32_t a[4][4], b[4][2];
#pragma unroll
            for (int mt = 0; mt < 4; mt++)
                LDSM4(a[mt][0], a[mt][1], a[mt][2], a[mt][3], aB + ch * 6144 + mt * 768);
#pragma unroll
            for (int p = 0; p < 2; p++)
                LDSM4(b[2 * p][0], b[2 * p][1], b[2 * p + 1][0], b[2 * p + 1][1],
                      bB + ch * 6144 + p * 16 * 48);
#pragma unroll
            for (int mt = 0; mt < 4; mt++)
#pragma unroll
                for (int nt = 0; nt < 4; nt++)
                    MMA16816(c[mt][nt][0], c[mt][nt][1], c[mt][nt][2], c[mt][nt][3],
                             a[mt][0], a[mt][1], a[mt][2], a[mt][3],
                             b[nt][0], b[nt][1]);
        }
        __syncthreads();
    }

    // ---- epilogue: act -> fp16 g_acth + per-tile max ----
    float rsv[8], w2v[8], ncv[8];
    const int n2 = 2 * (l & 3);
#pragma unroll
    for (int nt = 0; nt < 4; nt++)
#pragma unroll
        for (int e = 0; e < 2; e++) {
            int n = nBase + warp_n * 32 + nt * 8 + n2 + e;
            rsv[nt * 2 + e] = g_rsum[n];
            w2v[nt * 2 + e] = g_w2[n];
            ncv[nt * 2 + e] = NC[n];
        }
#pragma unroll
    for (int mt = 0; mt < 4; mt++) {
#pragma unroll
        for (int hf = 0; hf < 2; hf++) {
            int brow = mBase + warp_m * 64 + mt * 16 + (l >> 2) + hf * 8;
            float x2v = g_x2[brow];
            __half* orow = g_acth + (size_t)brow * NN;
            float rmax = 0.f;
#pragma unroll
            for (int nt = 0; nt < 4; nt++) {
                float act[2];
#pragma unroll
                for (int e = 0; e < 2; e++) {
                    int i = nt * 2 + e;
                    float dot = c[mt][nt][hf * 2 + e];
                    float rs = rsv[i];
                    float dist = (x2v + w2v[i]) - 2.0f * dot;
                    float dw = dist * (rs * (1.0f / 1024.0f));
                    act[e] = rs / ((rs + dw) + 1e-7f) * ncv[i];
                    rmax = fmaxf(rmax, act[e]);
                }
                int n0 = nBase + warp_n * 32 + nt * 8 + n2;
                __half2 ph = __floats2half2_rn(act[0], act[1]);
                *(uint32_t*)(orow + n0) = *(uint32_t*)&ph;
            }
            rmax = fmaxf(rmax, __shfl_xor_sync(0xFFFFFFFFu, rmax, 1));
            rmax = fmaxf(rmax, __shfl_xor_sync(0xFFFFFFFFu, rmax, 2));
            if ((l & 3) == 0)
                atomicMax(&g_tilemax[brow * 32 + blockIdx.x], __float_as_uint(rmax));
        }
    }
}

// ---------------------------------------------------------------------------
// K3: warp-per-row select (ballot-driven) + exact rescore + fused scatter
// ---------------------------------------------------------------------------
__global__ void __launch_bounds__(256)
k_select(const float* __restrict__ X, const float* __restrict__ W,
         const float* __restrict__ NC, float* __restrict__ sums) {
    const int l = threadIdx.x & 31;
    const int b = blockIdx.x * 8 + (threadIdx.x >> 5);

    // threshold from 32 tile maxima (one per lane)
    float tv = __uint_as_float(g_tilemax[b * 32 + l]);
    float m = tv;
#pragma unroll
    for (int o = 16; o > 0; o >>= 1)
        m = fmaxf(m, __shfl_xor_sync(0xFFFFFFFFu, m, o));
    const float thr = m - MARGIN;
    unsigned qmask = __ballot_sync(0xFFFFFFFFu, tv >= thr);

    // cache X row (32 floats per lane)
    const float4* x4 = (const float4*)(X + (size_t)b * DD);
    float4 xa[8];
#pragma unroll
    for (int j = 0; j < 8; j++) xa[j] = x4[l + j * 32];
    const float x2v = g_x2[b];

    unsigned long long best = 0ull;
    while (qmask) {
        const int T = __ffs(qmask) - 1;
        qmask &= qmask - 1;
        // 128 halves in tile T; lane reads 4
        uint2 hv = *(const uint2*)(g_acth + (size_t)b * NN + T * 128 + l * 4);
        __half2 h0 = *(__half2*)&hv.x, h1 = *(__half2*)&hv.y;
        float av[4] = {__low2float(h0), __high2float(h0),
                       __low2float(h1), __high2float(h1)};
#pragma unroll
        for (int q = 0; q < 4; q++) {
            unsigned cm = __ballot_sync(0xFFFFFFFFu, av[q] >= thr);
            while (cm) {
                const int cl = __ffs(cm) - 1;
                cm &= cm - 1;
                const int n = T * 128 + cl * 4 + q;
                // exact fp32 warp dot
                const float4* w4 = (const float4*)(W + (size_t)n * DD);
                float pv = 0.f;
#pragma unroll
                for (int j = 0; j < 8; j++) {
                    float4 w = w4[l + j * 32];
                    pv += xa[j].x * w.x + xa[j].y * w.y + xa[j].z * w.z + xa[j].w * w.w;
                }
#pragma unroll
                for (int o = 16; o > 0; o >>= 1)
                    pv += __shfl_xor_sync(0xFFFFFFFFu, pv, o);
                float rs = g_rsum[n];
                float dist = (x2v + g_w2[n]) - 2.0f * pv;
                float dw = dist * (rs * (1.0f / 1024.0f));
                float act = rs / ((rs + dw) + 1e-7f) * NC[n];
                unsigned long long kk =
                    ((unsigned long long)__float_as_uint(act) << 32) |
                    (unsigned int)(0xFFFFFFFFu - (unsigned int)n);
                best = (kk > best) ? kk : best;
            }
        }
    }
    if (l == 0) g_best[b] = best;

    // fused scatter (X row already in registers)
    float actw = __uint_as_float((unsigned int)(best >> 32));
    if (actw >= ATC) {
        int n = (int)(0xFFFFFFFFu - (unsigned int)best);
        if (l == 0) atomicAdd(&g_counts[n], 1.0f);
        float* sr = sums + (size_t)n * DD;
#pragma unroll
        for (int j = 0; j < 8; j++) {
            int d = (l + j * 32) * 4;
            atomicAdd(&sr[d + 0], xa[j].x);
            atomicAdd(&sr[d + 1], xa[j].y);
            atomicAdd(&sr[d + 2], xa[j].z);
            atomicAdd(&sr[d + 3], xa[j].w);
        }
    }
}

// ---------------------------------------------------------------------------
// K4: finalize
// ---------------------------------------------------------------------------
__global__ void k_final(const float* __restrict__ W, const float* __restrict__ MAVG,
                        float* __restrict__ out) {
    int n = blockIdx.x;
    int tid = threadIdx.x;
    float cnt = g_counts[n];
    float has = (cnt > 0.f) ? 1.f : 0.f;
    float cmax = fmaxf(cnt, 1.f);

    float* out0 = out;
    float* out1 = out + (size_t)NN * DD;
    float* out2 = out + 2 * (size_t)NN * DD;

    float4 sv = ((const float4*)(out0 + (size_t)n * DD))[tid];
    float4 wv = ((const float4*)(W + (size_t)n * DD))[tid];
    float4 av = ((const float4*)(MAVG + (size_t)n * DD))[tid];

    float mean[4] = {sv.x / cmax, sv.y / cmax, sv.z / cmax, sv.w / cmax};
    float wr[4] = {wv.x, wv.y, wv.z, wv.w};
    float ma[4] = {av.x, av.y, av.z, av.w};
    float mvn[4];
    float lmax = -FLT_MAX, lmin = FLT_MAX, lsum = 0.f;
#pragma unroll
    for (int j = 0; j < 4; j++) {
        float dist = fabsf(mean[j] - wr[j]);
        mvn[j] = ACOEF * dist + (1.0f - ACOEF) * ma[j];
        lmax = fmaxf(lmax, mvn[j]);
        lmin = fminf(lmin, mvn[j]);
        lsum += mvn[j];
    }
#pragma unroll
    for (int o = 16; o > 0; o >>= 1) {
        lmax = fmaxf(lmax, __shfl_down_sync(0xFFFFFFFFu, lmax, o));
        lmin = fminf(lmin, __shfl_down_sync(0xFFFFFFFFu, lmin, o));
        lsum += __shfl_down_sync(0xFFFFFFFFu, lsum, o);
    }
    __shared__ float smx[8], smn[8], ssm[8];
    __shared__ float rmx, rmn, rsm;
    int w = tid >> 5, l = tid & 31;
    if (l == 0) { smx[w] = lmax; smn[w] = lmin; ssm[w] = lsum; }
    __syncthreads();
    if (tid == 0) {
        float a = -FLT_MAX, b2 = FLT_MAX, cc = 0.f;
#pragma unroll
        for (int i = 0; i < 8; i++) {
            a = fmaxf(a, smx[i]); b2 = fminf(b2, smn[i]); cc += ssm[i];
        }
        rmx = a; rmn = b2; rsm = cc;
    }
    __syncthreads();
    float avg = rsm * (1.0f / 1024.0f);
    float scale = EPSDS * (rmx - rmn);

    float r0[4], r1[4], r2[4];
#pragma unroll
    for (int j = 0; j < 4; j++) {
        float t = (mvn[j] - avg) / scale;
        float r = 1.0f / (1.0f + expf(t));
        if (r != r) r = 1.0f;
        r0[j] = mean[j] * has;
        r1[j] = (wr[j] + LRC * (mean[j] - wr[j])) * has;
        r2[j] = r * has;
    }
    ((float4*)(out0 + (size_t)n * DD))[tid] = make_float4(r0[0], r0[1], r0[2], r0[3]);
    ((float4*)(out1 + (size_t)n * DD))[tid] = make_float4(r1[0], r1[1], r1[2], r1[3]);
    ((float4*)(out2 + (size_t)n * DD))[tid] = make_float4(r2[0], r2[1], r2[2], r2[3]);
}

// ---------------------------------------------------------------------------
extern "C" void kernel_launch(void* const* d_in, const int* in_sizes, int n_in,
                              void* d_out, int out_size) {
    const float* x    = (const float*)d_in[0];
    const float* wts  = (const float*)d_in[1];
    const float* rel  = (const float*)d_in[2];
    const float* mavg = (const float*)d_in[3];
    const float* nc   = (const float*)d_in[4];
    float* out = (float*)d_out;

    cudaFuncSetAttribute(k_gemm_bf16, cudaFuncAttributeMaxDynamicSharedMemorySize, GEMM_SMEM);

    k_init<<<(NN * DD / 4) / 256, 256>>>((float4*)out);
    k_rowprep<<<(BB + NN) / 8, 256>>>(x, wts, rel);
    dim3 g(NN / 128, BB / 128);
    k_gemm_bf16<<<g, 256, GEMM_SMEM>>>(nc);
    k_select<<<BB / 8, 256>>>(x, wts, nc, out);
    k_final<<<NN, 256>>>(wts, mavg, out);
}

// round 13
// speedup vs baseline: 1.0146x; 1.0146x over previous
#include <cuda_runtime.h>
#include <cuda_bf16.h>
#include <cuda_fp16.h>
#include <math.h>
#include <float.h>
#include <cstdint>

#define BB 8192
#define DD 1024
#define NN 4096
#define LRC 0.02f
#define ATC 0.3f
#define ACOEF 0.002f
#define EPSDS 0.5f
#define MARGIN 2e-3f
#define CAND_CAP (1 << 16)

// ---------------- device scratch ----------------
__device__ unsigned long long g_best[BB];
__device__ float g_x2[BB];
__device__ float g_w2[NN];
__device__ float g_rsum[NN];
__device__ float g_counts[NN];
__device__ unsigned int g_rowmax[BB];
__device__ int g_ncand;
__device__ unsigned int g_cand[CAND_CAP];
__device__ __nv_bfloat16 g_xb[BB * DD];       // 16 MB
__device__ __nv_bfloat16 g_wb[NN * DD];       // 8 MB
__device__ __half g_acth[(size_t)BB * NN];    // 32 MB fp16 acts

__device__ __forceinline__ uint32_t smem_u32(const void* p) {
    uint32_t a;
    asm("{ .reg .u64 t; cvta.to.shared.u64 t, %1; cvt.u32.u64 %0, t; }" : "=r"(a) : "l"(p));
    return a;
}

#define LDSM4(r0, r1, r2, r3, addr) \
    asm volatile("ldmatrix.sync.aligned.m8n8.x4.shared.b16 {%0,%1,%2,%3}, [%4];" \
                 : "=r"(r0), "=r"(r1), "=r"(r2), "=r"(r3) : "r"(addr))
#define MMA16816(c0, c1, c2, c3, a0, a1, a2, a3, b0, b1) \
    asm volatile("mma.sync.aligned.m16n8k16.row.col.f32.bf16.bf16.f32 " \
                 "{%0,%1,%2,%3}, {%4,%5,%6,%7}, {%8,%9}, {%0,%1,%2,%3};" \
                 : "+f"(c0), "+f"(c1), "+f"(c2), "+f"(c3) \
                 : "r"(a0), "r"(a1), "r"(a2), "r"(a3), "r"(b0), "r"(b1))
#define CPASYNC16(dst, src) \
    asm volatile("cp.async.ca.shared.global [%0], [%1], 16;" :: "r"(dst), "l"(src))
#define CPCOMMIT() asm volatile("cp.async.commit_group;" ::: "memory")
#define CPWAIT1() asm volatile("cp.async.wait_group 1;" ::: "memory")

static constexpr int STAGE_B = 24576;
static constexpr int GEMM_SMEM = 3 * STAGE_B;   // 73728

// ---------------------------------------------------------------------------
// K0: zero sums region + counters
// ---------------------------------------------------------------------------
__global__ void k_init(float4* __restrict__ sums4) {
    int i = blockIdx.x * blockDim.x + threadIdx.x;
    sums4[i] = make_float4(0.f, 0.f, 0.f, 0.f);
    if (i < NN) g_counts[i] = 0.f;
    if (i < BB) { g_rowmax[i] = 0u; g_best[i] = 0ull; }
    if (i == 0) g_ncand = 0;
}

// ---------------------------------------------------------------------------
// K1: row reductions + bf16 conversion (warp per row)
// ---------------------------------------------------------------------------
__global__ void __launch_bounds__(256)
k_rowprep(const float* __restrict__ X, const float* __restrict__ W,
          const float* __restrict__ REL) {
    const int wid = threadIdx.x >> 5, l = threadIdx.x & 31;
    const int r = blockIdx.x * 8 + wid;
    float v1 = 0.f, v2 = 0.f;
    if (r < BB) {
        const float4* xr = (const float4*)(X + (size_t)r * DD);
        uint2* ob = (uint2*)(g_xb + (size_t)r * DD);
#pragma unroll
        for (int j = 0; j < 8; j++) {
            float4 v = xr[l + j * 32];
            v1 += v.x * v.x + v.y * v.y + v.z * v.z + v.w * v.w;
            __nv_bfloat162 p0 = __floats2bfloat162_rn(v.x, v.y);
            __nv_bfloat162 p1 = __floats2bfloat162_rn(v.z, v.w);
            ob[l + j * 32] = make_uint2(*(uint32_t*)&p0, *(uint32_t*)&p1);
        }
    } else {
        const int n = r - BB;
        const float4* wr = (const float4*)(W + (size_t)n * DD);
        const float4* rr = (const float4*)(REL + (size_t)n * DD);
        uint2* ob = (uint2*)(g_wb + (size_t)n * DD);
#pragma unroll
        for (int j = 0; j < 8; j++) {
            float4 v = wr[l + j * 32];
            float4 rv = rr[l + j * 32];
            v1 += v.x * v.x + v.y * v.y + v.z * v.z + v.w * v.w;
            v2 += rv.x + rv.y + rv.z + rv.w;
            __nv_bfloat162 p0 = __floats2bfloat162_rn(v.x, v.y);
            __nv_bfloat162 p1 = __floats2bfloat162_rn(v.z, v.w);
            ob[l + j * 32] = make_uint2(*(uint32_t*)&p0, *(uint32_t*)&p1);
        }
    }
#pragma unroll
    for (int o = 16; o > 0; o >>= 1) {
        v1 += __shfl_down_sync(0xFFFFFFFFu, v1, o);
        v2 += __shfl_down_sync(0xFFFFFFFFu, v2, o);
    }
    if (l == 0) {
        if (r < BB) g_x2[r] = v1;
        else { g_w2[r - BB] = v1; g_rsum[r - BB] = v2; }
    }
}

// ---------------------------------------------------------------------------
// K2: bf16 mma.sync GEMM (128x128 tile, 3-stage cp.async)
// ---------------------------------------------------------------------------
__global__ void __launch_bounds__(256, 2)
k_gemm_bf16(const float* __restrict__ NC) {
    extern __shared__ __align__(128) char sm[];
    const uint32_t sb = smem_u32(sm);

    const int tid = threadIdx.x;
    const int l = tid & 31, wid = tid >> 5;
    const int warp_m = wid >> 2, warp_n = wid & 3;
    const int mBase = blockIdx.y * 128;
    const int nBase = blockIdx.x * 128;

    const int row = tid >> 1, h = tid & 1;
    const __nv_bfloat16* xg = g_xb + (size_t)(mBase + row) * DD + h * 16;
    const __nv_bfloat16* wg = g_wb + (size_t)(nBase + row) * DD + h * 16;
    const uint32_t aDst = sb + h * 6144 + row * 48;
    const uint32_t bDst = sb + 12288 + h * 6144 + row * 48;

#pragma unroll
    for (int s = 0; s < 2; s++) {
        const __nv_bfloat16* xs = xg + s * 32;
        const __nv_bfloat16* ws = wg + s * 32;
        CPASYNC16(aDst + s * STAGE_B, xs);
        CPASYNC16(aDst + s * STAGE_B + 16, xs + 8);
        CPASYNC16(bDst + s * STAGE_B, ws);
        CPASYNC16(bDst + s * STAGE_B + 16, ws + 8);
        CPCOMMIT();
    }

    float c[4][4][4];
#pragma unroll
    for (int i = 0; i < 4; i++)
#pragma unroll
        for (int j = 0; j < 4; j++)
#pragma unroll
            for (int k = 0; k < 4; k++) c[i][j][k] = 0.f;

    const uint32_t aAddr0 = sb + (warp_m * 64 + (l & 15)) * 48 + (l >> 4) * 16;
    const int b_nt_off = (l >> 4) & 1;
    const int b_half = (l >> 3) & 1;
    const uint32_t bAddr0 = sb + 12288 +
        (warp_n * 32 + b_nt_off * 8 + (l & 7)) * 48 + b_half * 16;

    for (int kt = 0; kt < 32; kt++) {
        CPWAIT1();
        __syncthreads();
        if (kt + 2 < 32) {
            const int s = (kt + 2) % 3;
            const __nv_bfloat16* xs = xg + (kt + 2) * 32;
            const __nv_bfloat16* ws = wg + (kt + 2) * 32;
            CPASYNC16(aDst + s * STAGE_B, xs);
            CPASYNC16(aDst + s * STAGE_B + 16, xs + 8);
            CPASYNC16(bDst + s * STAGE_B, ws);
            CPASYNC16(bDst + s * STAGE_B + 16, ws + 8);
        }
        CPCOMMIT();

        const uint32_t aB = aAddr0 + (kt % 3) * STAGE_B;
        const uint32_t bB = bAddr0 + (kt % 3) * STAGE_B;
#pragma unroll
        for (int ch = 0; ch < 2; ch++) {
            uint32_t a[4][4], b[4][2];
#pragma unroll
            for (int mt = 0; mt < 4; mt++)
                LDSM4(a[mt][0], a[mt][1], a[mt][2], a[mt][3], aB + ch * 6144 + mt * 768);
#pragma unroll
            for (int p = 0; p < 2; p++)
                LDSM4(b[2 * p][0], b[2 * p][1], b[2 * p + 1][0], b[2 * p + 1][1],
                      bB + ch * 6144 + p * 16 * 48);
#pragma unroll
            for (int mt = 0; mt < 4; mt++)
#pragma unroll
                for (int nt = 0; nt < 4; nt++)
                    MMA16816(c[mt][nt][0], c[mt][nt][1], c[mt][nt][2], c[mt][nt][3],
                             a[mt][0], a[mt][1], a[mt][2], a[mt][3],
                             b[nt][0], b[nt][1]);
        }
        __syncthreads();
    }

    // ---- epilogue: act -> fp16 g_acth + rowmax ----
    float rsv[8], w2v[8], ncv[8];
    const int n2 = 2 * (l & 3);
#pragma unroll
    for (int nt = 0; nt < 4; nt++)
#pragma unroll
        for (int e = 0; e < 2; e++) {
            int n = nBase + warp_n * 32 + nt * 8 + n2 + e;
            rsv[nt * 2 + e] = g_rsum[n];
            w2v[nt * 2 + e] = g_w2[n];
            ncv[nt * 2 + e] = NC[n];
        }
#pragma unroll
    for (int mt = 0; mt < 4; mt++) {
#pragma unroll
        for (int hf = 0; hf < 2; hf++) {
            int brow = mBase + warp_m * 64 + mt * 16 + (l >> 2) + hf * 8;
            float x2v = g_x2[brow];
            __half* orow = g_acth + (size_t)brow * NN;
            float rmax = 0.f;
#pragma unroll
            for (int nt = 0; nt < 4; nt++) {
                float act[2];
#pragma unroll
                for (int e = 0; e < 2; e++) {
                    int i = nt * 2 + e;
                    float dot = c[mt][nt][hf * 2 + e];
                    float rs = rsv[i];
                    float dist = (x2v + w2v[i]) - 2.0f * dot;
                    float dw = dist * (rs * (1.0f / 1024.0f));
                    act[e] = rs / ((rs + dw) + 1e-7f) * ncv[i];
                    rmax = fmaxf(rmax, act[e]);
                }
                int n0 = nBase + warp_n * 32 + nt * 8 + n2;
                __half2 ph = __floats2half2_rn(act[0], act[1]);
                *(uint32_t*)(orow + n0) = *(uint32_t*)&ph;
            }
            rmax = fmaxf(rmax, __shfl_xor_sync(0xFFFFFFFFu, rmax, 1));
            rmax = fmaxf(rmax, __shfl_xor_sync(0xFFFFFFFFu, rmax, 2));
            if ((l & 3) == 0)
                atomicMax(&g_rowmax[brow], __float_as_uint(rmax));
        }
    }
}

// ---------------------------------------------------------------------------
// K3a: candidate compaction, 4 rows/block, strided MLP-8 scan
// ---------------------------------------------------------------------------
__global__ void __launch_bounds__(256)
k_cand() {
    const int tid = threadIdx.x;
    const int b0 = blockIdx.x * 4;
    __shared__ float sthr[4];
    if (tid < 4) sthr[tid] = __uint_as_float(g_rowmax[b0 + tid]) - MARGIN;
    __syncthreads();

    const uint4* base = (const uint4*)(g_acth + (size_t)b0 * NN);  // 2048 uint4
    uint4 v[8];
#pragma unroll
    for (int i = 0; i < 8; i++) v[i] = base[tid + i * 256];
#pragma unroll
    for (int i = 0; i < 8; i++) {
        const int idx = tid + i * 256;
        const int row = idx >> 9;             // 512 uint4 per row
        const float thr = sthr[row];
        const int nb = (idx & 511) * 8;       // half index within row
        uint32_t ws[4] = {v[i].x, v[i].y, v[i].z, v[i].w};
#pragma unroll
        for (int q = 0; q < 4; q++) {
            __half2 h2 = *(__half2*)&ws[q];
            float a0 = __low2float(h2), a1 = __high2float(h2);
            if (a0 >= thr) {
                int p = atomicAdd(&g_ncand, 1);
                if (p < CAND_CAP)
                    g_cand[p] = ((unsigned)(b0 + row) << 12) | (unsigned)(nb + q * 2);
            }
            if (a1 >= thr) {
                int p = atomicAdd(&g_ncand, 1);
                if (p < CAND_CAP)
                    g_cand[p] = ((unsigned)(b0 + row) << 12) | (unsigned)(nb + q * 2 + 1);
            }
        }
    }
}

// ---------------------------------------------------------------------------
// K3b: exact fp32 rescore, one candidate per warp
// ---------------------------------------------------------------------------
__global__ void __launch_bounds__(256)
k_rescore(const float* __restrict__ X, const float* __restrict__ W,
          const float* __restrict__ NC) {
    const int l = threadIdx.x & 31;
    const int gw = blockIdx.x * 8 + (threadIdx.x >> 5);
    const int total = min(g_ncand, CAND_CAP);
    for (int ci = gw; ci < total; ci += gridDim.x * 8) {
        unsigned cd = g_cand[ci];
        int b = cd >> 12, n = cd & 4095;
        const float4* x4 = (const float4*)(X + (size_t)b * DD);
        const float4* w4 = (const float4*)(W + (size_t)n * DD);
        float p = 0.f;
#pragma unroll
        for (int j = 0; j < 8; j++) {
            float4 a = x4[l + j * 32], w = w4[l + j * 32];
            p += a.x * w.x + a.y * w.y + a.z * w.z + a.w * w.w;
        }
#pragma unroll
        for (int o = 16; o > 0; o >>= 1) p += __shfl_down_sync(0xFFFFFFFFu, p, o);
        if (l == 0) {
            float rs = g_rsum[n];
            float dist = (g_x2[b] + g_w2[n]) - 2.0f * p;
            float dw = dist * (rs * (1.0f / 1024.0f));
            float act = rs / ((rs + dw) + 1e-7f) * NC[n];
            unsigned long long kk =
                ((unsigned long long)__float_as_uint(act) << 32) |
                (unsigned int)(0xFFFFFFFFu - (unsigned int)n);
            atomicMax(&g_best[b], kk);
        }
    }
}

// ---------------------------------------------------------------------------
// K4: scatter
// ---------------------------------------------------------------------------
__global__ void k_scatter(const float* __restrict__ X, float* __restrict__ sums) {
    int b = blockIdx.x;
    unsigned long long key = g_best[b];
    float act = __uint_as_float((unsigned int)(key >> 32));
    if (!(act >= ATC)) return;
    int n = (int)(0xFFFFFFFFu - (unsigned int)key);
    if (threadIdx.x == 0) atomicAdd(&g_counts[n], 1.0f);
    const float* xr = X + (size_t)b * DD;
    float* sr = sums + (size_t)n * DD;
#pragma unroll
    for (int k = 0; k < 4; k++) {
        int d = threadIdx.x + k * 256;
        atomicAdd(&sr[d], xr[d]);
    }
}

// ---------------------------------------------------------------------------
// K5: finalize
// ---------------------------------------------------------------------------
__global__ void k_final(const float* __restrict__ W, const float* __restrict__ MAVG,
                        float* __restrict__ out) {
    int n = blockIdx.x;
    int tid = threadIdx.x;
    float cnt = g_counts[n];
    float has = (cnt > 0.f) ? 1.f : 0.f;
    float cmax = fmaxf(cnt, 1.f);

    float* out0 = out;
    float* out1 = out + (size_t)NN * DD;
    float* out2 = out + 2 * (size_t)NN * DD;

    float4 sv = ((const float4*)(out0 + (size_t)n * DD))[tid];
    float4 wv = ((const float4*)(W + (size_t)n * DD))[tid];
    float4 av = ((const float4*)(MAVG + (size_t)n * DD))[tid];

    float mean[4] = {sv.x / cmax, sv.y / cmax, sv.z / cmax, sv.w / cmax};
    float wr[4] = {wv.x, wv.y, wv.z, wv.w};
    float ma[4] = {av.x, av.y, av.z, av.w};
    float mvn[4];
    float lmax = -FLT_MAX, lmin = FLT_MAX, lsum = 0.f;
#pragma unroll
    for (int j = 0; j < 4; j++) {
        float dist = fabsf(mean[j] - wr[j]);
        mvn[j] = ACOEF * dist + (1.0f - ACOEF) * ma[j];
        lmax = fmaxf(lmax, mvn[j]);
        lmin = fminf(lmin, mvn[j]);
        lsum += mvn[j];
    }
#pragma unroll
    for (int o = 16; o > 0; o >>= 1) {
        lmax = fmaxf(lmax, __shfl_down_sync(0xFFFFFFFFu, lmax, o));
        lmin = fminf(lmin, __shfl_down_sync(0xFFFFFFFFu, lmin, o));
        lsum += __shfl_down_sync(0xFFFFFFFFu, lsum, o);
    }
    __shared__ float smx[8], smn[8], ssm[8];
    __shared__ float rmx, rmn, rsm;
    int w = tid >> 5, l = tid & 31;
    if (l == 0) { smx[w] = lmax; smn[w] = lmin; ssm[w] = lsum; }
    __syncthreads();
    if (tid == 0) {
        float a = -FLT_MAX, b2 = FLT_MAX, cc = 0.f;
#pragma unroll
        for (int i = 0; i < 8; i++) {
            a = fmaxf(a, smx[i]); b2 = fminf(b2, smn[i]); cc += ssm[i];
        }
        rmx = a; rmn = b2; rsm = cc;
    }
    __syncthreads();
    float avg = rsm * (1.0f / 1024.0f);
    float scale = EPSDS * (rmx - rmn);

    float r0[4], r1[4], r2[4];
#pragma unroll
    for (int j = 0; j < 4; j++) {
        float t = (mvn[j] - avg) / scale;
        float r = 1.0f / (1.0f + expf(t));
        if (r != r) r = 1.0f;
        r0[j] = mean[j] * has;
        r1[j] = (wr[j] + LRC * (mean[j] - wr[j])) * has;
        r2[j] = r * has;
    }
    ((float4*)(out0 + (size_t)n * DD))[tid] = make_float4(r0[0], r0[1], r0[2], r0[3]);
    ((float4*)(out1 + (size_t)n * DD))[tid] = make_float4(r1[0], r1[1], r1[2], r1[3]);
    ((float4*)(out2 + (size_t)n * DD))[tid] = make_float4(r2[0], r2[1], r2[2], r2[3]);
}

// ---------------------------------------------------------------------------
extern "C" void kernel_launch(void* const* d_in, const int* in_sizes, int n_in,
                              void* d_out, int out_size) {
    const float* x    = (const float*)d_in[0];
    const float* wts  = (const float*)d_in[1];
    const float* rel  = (const float*)d_in[2];
    const float* mavg = (const float*)d_in[3];
    const float* nc   = (const float*)d_in[4];
    float* out = (float*)d_out;

    cudaFuncSetAttribute(k_gemm_bf16, cudaFuncAttributeMaxDynamicSharedMemorySize, GEMM_SMEM);

    k_init<<<(NN * DD / 4) / 256, 256>>>((float4*)out);
    k_rowprep<<<(BB + NN) / 8, 256>>>(x, wts, rel);
    dim3 g(NN / 128, BB / 128);
    k_gemm_bf16<<<g, 256, GEMM_SMEM>>>(nc);
    k_cand<<<BB / 4, 256>>>();
    k_rescore<<<512, 256>>>(x, wts, nc);
    k_scatter<<<BB, 256>>>(x, out);
    k_final<<<NN, 256>>>(wts, mavg, out);
}